// round 14
// baseline (speedup 1.0000x reference)
#include <cuda_runtime.h>
#include <cuda_bf16.h>
#include <cstdint>
#include <cstddef>

#define B_   64
#define T_   512
#define DIN  1024
#define DH   2048
#define DOUT 1024
#define M1   (B_ * T_)   // 32768

// Recurrence persistent kernel: 128 blocks = 16 ntiles(128 col) x 8 kchunks(256 K)
#define NBLK    128
#define NTHR    256      // 8 warps: (kh, mh, nh)
#define KGG     128      // k16-groups over DH
#define WTILE_U4 8192    // W tile uint4s per block (128KB)

// ---------------------------------------------------------------------------
// Device globals (allocation-free scratch)
// ---------------------------------------------------------------------------
__device__ float    g_xh[(size_t)M1 * DH];        // 256 MB input projection (fp32)
__device__ float    g_h[B_ * DH];                 // final hidden state (fp32)
// W_h2h bf16 hi/lo packed in m16n8k16 B-fragment order, per block tile:
// uint4 {b0_hi, b1_hi, b0_lo, b1_lo} per (block, kg, nfl, lane)
__device__ uint4    g_Wf[(size_t)NBLK * WTILE_U4];   // 16 MB
// h bf16 hi/lo packed in A-fragment order:
// uint4 {a0,a1,a2,a3} per (kgg, mf, plane, lane)
__device__ uint4    g_hf[KGG * 4 * 2 * 32];          // 512 KB
__device__ float    g_part[16][B_][DH];              // split-K partials, 8 MB
__device__ unsigned g_bar_count;
__device__ unsigned g_bar_phase;

__device__ __forceinline__ float2 ffma2(float2 a, float2 b, float2 c) {
    float2 d;
    asm("fma.rn.f32x2 %0, %1, %2, %3;"
        : "=l"(reinterpret_cast<unsigned long long&>(d))
        : "l"(reinterpret_cast<unsigned long long&>(a)),
          "l"(reinterpret_cast<unsigned long long&>(b)),
          "l"(reinterpret_cast<unsigned long long&>(c)));
    return d;
}

// split (v0, v1) into bf16 hi plane + bf16 lo (residual) plane, packed bf16x2
__device__ __forceinline__ void split2(float v0, float v1,
                                       unsigned& hi, unsigned& lo) {
    __nv_bfloat162 h2 = __floats2bfloat162_rn(v0, v1);
    float2 hf = __bfloat1622float2(h2);
    __nv_bfloat162 l2 = __floats2bfloat162_rn(v0 - hf.x, v1 - hf.y);
    hi = *reinterpret_cast<unsigned*>(&h2);
    lo = *reinterpret_cast<unsigned*>(&l2);
}

__device__ __forceinline__ void mma_bf16(float* c, const uint4& a,
                                         unsigned b0, unsigned b1) {
    asm volatile(
        "mma.sync.aligned.m16n8k16.row.col.f32.bf16.bf16.f32 "
        "{%0,%1,%2,%3}, {%4,%5,%6,%7}, {%8,%9}, {%0,%1,%2,%3};"
        : "+f"(c[0]), "+f"(c[1]), "+f"(c[2]), "+f"(c[3])
        : "r"(a.x), "r"(a.y), "r"(a.z), "r"(a.w), "r"(b0), "r"(b1));
}

// ---------------------------------------------------------------------------
// Kernel 1 (NEW): g_xh = x @ W_x2h^T + b_x2h via bf16x3 tensor-core MMA.
// 128x128 tile, Kc=32 double-buffered fragment-order SMEM, 8 warps (4m x 2n).
// ---------------------------------------------------------------------------
__global__ __launch_bounds__(256) void k_xh_tc(const float* __restrict__ A,
                                               const float* __restrict__ W,
                                               const float* __restrict__ bias) {
    extern __shared__ uint4 smem[];
    uint4* sA = smem;          // [buf][kg][mf 0..7][plane 0..1][lane] : 2048 uint4
    uint4* sB = smem + 2048;   // [buf][kg][nfl 0..15][lane]          : 2048 uint4

    const int tid  = threadIdx.x;
    const int warp = tid >> 5;
    const int lane = tid & 31;
    const int wm = warp >> 1;      // 0..3 : rows wm*32..+31
    const int wn = warp & 1;       // 0..1 : cols wn*64..+63
    const int m0 = blockIdx.y * 128;
    const int n0 = blockIdx.x * 128;
    const int lr = lane >> 2;      // 0..7
    const int lk = (lane & 3) * 2;

    // loader base pointers (thread owns: A item (mf=warp, lane), kg 0/1;
    //                                  W items (nfl=warp, warp+8, lane), kg 0/1)
    const float* Ab = A + (size_t)(m0 + warp * 16 + lr) * DIN + lk;
    const float* Wb0 = W + (size_t)(n0 + warp * 8 + lr) * DIN + lk;
    const float* Wb1 = W + (size_t)(n0 + (warp + 8) * 8 + lr) * DIN + lk;

    float acc[2][8][4];
#pragma unroll
    for (int mi = 0; mi < 2; mi++)
#pragma unroll
        for (int nf = 0; nf < 8; nf++)
#pragma unroll
            for (int i = 0; i < 4; i++) acc[mi][nf][i] = 0.f;

    float2 ax[2][4];        // [kg][{(r,k),(r+8,k),(r,k+8),(r+8,k+8)}]
    float2 wx[2][2][2];     // [kg][nfl half][k01 / k89]

    auto gload = [&](int kc) {
#pragma unroll
        for (int kg = 0; kg < 2; kg++) {
            const float* ap = Ab + kc + kg * 16;
            ax[kg][0] = __ldg((const float2*)ap);
            ax[kg][1] = __ldg((const float2*)(ap + 8 * DIN));
            ax[kg][2] = __ldg((const float2*)(ap + 8));
            ax[kg][3] = __ldg((const float2*)(ap + 8 * DIN + 8));
            const float* wp0 = Wb0 + kc + kg * 16;
            const float* wp1 = Wb1 + kc + kg * 16;
            wx[kg][0][0] = __ldg((const float2*)wp0);
            wx[kg][0][1] = __ldg((const float2*)(wp0 + 8));
            wx[kg][1][0] = __ldg((const float2*)wp1);
            wx[kg][1][1] = __ldg((const float2*)(wp1 + 8));
        }
    };

    auto sstore = [&](int buf) {
#pragma unroll
        for (int kg = 0; kg < 2; kg++) {
            uint4 hi, lo;
            split2(ax[kg][0].x, ax[kg][0].y, hi.x, lo.x);
            split2(ax[kg][1].x, ax[kg][1].y, hi.y, lo.y);
            split2(ax[kg][2].x, ax[kg][2].y, hi.z, lo.z);
            split2(ax[kg][3].x, ax[kg][3].y, hi.w, lo.w);
            sA[buf * 1024 + kg * 512 + warp * 64 + lane]      = hi;
            sA[buf * 1024 + kg * 512 + warp * 64 + 32 + lane] = lo;
            uint4 v0, v1;
            split2(wx[kg][0][0].x, wx[kg][0][0].y, v0.x, v0.z);
            split2(wx[kg][0][1].x, wx[kg][0][1].y, v0.y, v0.w);
            split2(wx[kg][1][0].x, wx[kg][1][0].y, v1.x, v1.z);
            split2(wx[kg][1][1].x, wx[kg][1][1].y, v1.y, v1.w);
            sB[buf * 1024 + kg * 512 + warp * 32 + lane]       = v0;
            sB[buf * 1024 + kg * 512 + (warp + 8) * 32 + lane] = v1;
        }
    };

    auto compute = [&](int buf) {
#pragma unroll
        for (int kg = 0; kg < 2; kg++) {
            const int ab = buf * 1024 + kg * 512;
            uint4 Ah0 = sA[ab + (wm * 2) * 64 + lane];
            uint4 Al0 = sA[ab + (wm * 2) * 64 + 32 + lane];
            uint4 Ah1 = sA[ab + (wm * 2 + 1) * 64 + lane];
            uint4 Al1 = sA[ab + (wm * 2 + 1) * 64 + 32 + lane];
#pragma unroll
            for (int nf = 0; nf < 8; nf++) {
                uint4 w = sB[ab + (wn * 8 + nf) * 32 + lane];
                mma_bf16(acc[0][nf], Ah0, w.x, w.y);   // hi*hi
                mma_bf16(acc[0][nf], Al0, w.x, w.y);   // lo*hi
                mma_bf16(acc[0][nf], Ah0, w.z, w.w);   // hi*lo
                mma_bf16(acc[1][nf], Ah1, w.x, w.y);
                mma_bf16(acc[1][nf], Al1, w.x, w.y);
                mma_bf16(acc[1][nf], Ah1, w.z, w.w);
            }
        }
    };

    gload(0);
    sstore(0);
    __syncthreads();

    for (int kc = 0; kc < DIN; kc += 32) {
        const int buf = (kc >> 5) & 1;
        const bool more = (kc + 32) < DIN;
        if (more) gload(kc + 32);
        compute(buf);
        if (more) sstore(buf ^ 1);
        __syncthreads();
    }

    // epilogue: add bias, store fp32
#pragma unroll
    for (int nf = 0; nf < 8; nf++) {
        const int c = n0 + wn * 64 + nf * 8 + lk;
        float2 bb = __ldg((const float2*)(bias + c));
#pragma unroll
        for (int mi = 0; mi < 2; mi++) {
            const int r = m0 + wm * 32 + mi * 16 + lr;
            *(float2*)(g_xh + (size_t)r * DH + c) =
                make_float2(acc[mi][nf][0] + bb.x, acc[mi][nf][1] + bb.y);
            *(float2*)(g_xh + (size_t)(r + 8) * DH + c) =
                make_float2(acc[mi][nf][2] + bb.x, acc[mi][nf][3] + bb.y);
        }
    }
}

// ---------------------------------------------------------------------------
// Pack W_h2h into bf16 hi/lo B-fragment order (per-block 128KB tiles).
// ---------------------------------------------------------------------------
__global__ void k_packw(const float* __restrict__ W) {
    size_t u = (size_t)blockIdx.x * 256 + threadIdx.x;   // 0 .. 1M-1
    int b    = (int)(u >> 13);
    int r    = (int)(u & 8191);
    int kg   = r >> 9;          // 0..15
    int nfl  = (r >> 5) & 15;   // 0..15
    int lane = r & 31;
    int nt = b >> 3, kch = b & 7;
    int n = nt * 128 + nfl * 8 + (lane >> 2);
    int k = kch * 256 + kg * 16 + (lane & 3) * 2;
    const float* row = W + (size_t)n * DH;
    float w0 = row[k],     w1 = row[k + 1];
    float w2 = row[k + 8], w3 = row[k + 9];
    uint4 v;
    unsigned lo01, lo89;
    split2(w0, w1, v.x, lo01);
    split2(w2, w3, v.y, lo89);
    v.z = lo01;
    v.w = lo89;
    g_Wf[u] = v;
}

// ---------------------------------------------------------------------------
// Persistent recurrence kernel: bf16x3 mma.m16n8k16, W tile persistent in SMEM,
// 8 warps (2/SMSP), A fragments L2-direct, 16-way split-K partials.
// xh loads for the epilogue are hoisted above the MMA phase (DRAM latency hide).
// ---------------------------------------------------------------------------
__global__ __launch_bounds__(NTHR, 1) void k_recur() {
    extern __shared__ uint4 sW[];   // 8192 uint4 = 128 KB

    const int tid  = threadIdx.x;
    const int b    = blockIdx.x;
    const int warp = tid >> 5;
    const int lane = tid & 31;
    const int kh = warp >> 2;          // k-half (0/1): 128 K each
    const int mh = (warp >> 1) & 1;    // m-half: rows mh*32..+31
    const int nh = warp & 1;           // n-half: cols nh*64..+63
    const int nt  = b >> 3;            // ntile 0..15
    const int kch = b & 7;             // kchunk 0..7
    const int pk  = kch * 2 + kh;      // partial buffer index

    // Load persistent W tile into SMEM (once)
    {
        const uint4* wsrc = g_Wf + (size_t)b * WTILE_U4;
        for (int i = tid; i < WTILE_U4; i += NTHR) sW[i] = __ldg(wsrc + i);
    }

    // replay-safe grid barrier
    unsigned bar_base;
    asm volatile("ld.acquire.gpu.global.u32 %0, [%1];"
                 : "=r"(bar_base) : "l"(&g_bar_phase));
    unsigned bar_t = 0;

    auto grid_bar = [&]() {
        bar_t++;
        __syncthreads();
        __threadfence();
        if (tid == 0) {
            unsigned arr = atomicAdd(&g_bar_count, 1);
            if (arr == NBLK - 1) {
                atomicExch(&g_bar_count, 0);
                __threadfence();
                atomicAdd(&g_bar_phase, 1);
            } else {
                unsigned p;
                do {
                    __nanosleep(32);
                    asm volatile("ld.acquire.gpu.global.u32 %0, [%1];"
                                 : "=r"(p) : "l"(&g_bar_phase));
                } while (p - bar_base < bar_t);
            }
        }
        __syncthreads();
    };

    // Epilogue mapping: block b owns kgg = b (16 h-columns), threads 0..127
    const int elane = tid & 31;
    const int emf   = (tid >> 5) & 3;
    const int er    = emf * 16 + (elane >> 2);       // row (and +8)
    const int ek0   = b * 16 + (elane & 3) * 2;      // col (and +1, +8, +9)
    uint4* hf_hi = g_hf + ((b * 4 + emf) * 2 + 0) * 32 + elane;
    uint4* hf_lo = g_hf + ((b * 4 + emf) * 2 + 1) * 32 + elane;

    // preloaded xh values for epilogue of step s (loads xh_{s-1})
    auto xh_load = [&](int s, float2& v00, float2& v01, float2& v10, float2& v11) {
        const float* x0 = &g_xh[((size_t)er * T_ + (s - 1)) * DH + ek0];
        const float* x1 = &g_xh[((size_t)(er + 8) * T_ + (s - 1)) * DH + ek0];
        v00 = __ldg((const float2*)x0);
        v01 = __ldg((const float2*)(x0 + 8));
        v10 = __ldg((const float2*)x1);
        v11 = __ldg((const float2*)(x1 + 8));
    };

    auto epilogue = [&](int s, float2 v00, float2 v01, float2 v10, float2 v11,
                        bool addp) {
        if (addp) {
#pragma unroll
            for (int p = 0; p < 16; p++) {
                const float* pb = &g_part[p][0][0];
                const float* p0 = pb + (size_t)er * DH + ek0;
                const float* p1 = pb + (size_t)(er + 8) * DH + ek0;
                float2 q;
                q = __ldcg((const float2*)p0);       v00.x += q.x; v00.y += q.y;
                q = __ldcg((const float2*)(p0 + 8)); v01.x += q.x; v01.y += q.y;
                q = __ldcg((const float2*)p1);       v10.x += q.x; v10.y += q.y;
                q = __ldcg((const float2*)(p1 + 8)); v11.x += q.x; v11.y += q.y;
            }
        }
        v00.x = fmaxf(v00.x, 0.f); v00.y = fmaxf(v00.y, 0.f);
        v01.x = fmaxf(v01.x, 0.f); v01.y = fmaxf(v01.y, 0.f);
        v10.x = fmaxf(v10.x, 0.f); v10.y = fmaxf(v10.y, 0.f);
        v11.x = fmaxf(v11.x, 0.f); v11.y = fmaxf(v11.y, 0.f);
        uint4 hi, lo;
        split2(v00.x, v00.y, hi.x, lo.x);   // a0: (r,   k0,k0+1)
        split2(v10.x, v10.y, hi.y, lo.y);   // a1: (r+8, k0,k0+1)
        split2(v01.x, v01.y, hi.z, lo.z);   // a2: (r,   k0+8,k0+9)
        split2(v11.x, v11.y, hi.w, lo.w);   // a3: (r+8, k0+8,k0+9)
        *hf_hi = hi;
        *hf_lo = lo;
        if (s == T_) {
            *(float2*)&g_h[(size_t)er * DH + ek0]           = v00;
            *(float2*)&g_h[(size_t)er * DH + ek0 + 8]       = v01;
            *(float2*)&g_h[(size_t)(er + 8) * DH + ek0]     = v10;
            *(float2*)&g_h[(size_t)(er + 8) * DH + ek0 + 8] = v11;
        }
    };

    if (tid < 128) {   // h_1 = relu(xh_0)
        float2 v00, v01, v10, v11;
        xh_load(1, v00, v01, v10, v11);
        epilogue(1, v00, v01, v10, v11, false);
    }
    grid_bar();

    const int kggbase = kch * 16 + kh * 8;

    for (int s = 2; s <= T_; s++) {
        // hoisted epilogue xh loads for this step (hide DRAM latency under MMA)
        float2 pv00, pv01, pv10, pv11;
        if (tid < 128) xh_load(s, pv00, pv01, pv10, pv11);

        // ---- MMA phase: partial[pk] = h_{s-1}[:, kslice] @ W[ntile, kslice]^T
        float acc[2][8][4];
#pragma unroll
        for (int mi = 0; mi < 2; mi++)
#pragma unroll
            for (int nf = 0; nf < 8; nf++)
#pragma unroll
                for (int i = 0; i < 4; i++) acc[mi][nf][i] = 0.f;

        // prefetch kg=0 A fragments
        const uint4* ab0 = g_hf + ((kggbase * 4 + mh * 2) * 2) * 32 + lane;
        uint4 A0h = __ldcg(ab0);
        uint4 A0l = __ldcg(ab0 + 32);
        uint4 A1h = __ldcg(ab0 + 64);
        uint4 A1l = __ldcg(ab0 + 96);

#pragma unroll
        for (int kg = 0; kg < 8; kg++) {
            uint4 N0h, N0l, N1h, N1l;
            if (kg < 7) {
                const uint4* ab =
                    g_hf + (((kggbase + kg + 1) * 4 + mh * 2) * 2) * 32 + lane;
                N0h = __ldcg(ab);
                N0l = __ldcg(ab + 32);
                N1h = __ldcg(ab + 64);
                N1l = __ldcg(ab + 96);
            }
            const int wb = ((kh * 8 + kg) * 16 + nh * 8) * 32 + lane;
#pragma unroll
            for (int nf = 0; nf < 8; nf++) {
                uint4 w = sW[wb + nf * 32];
                mma_bf16(acc[0][nf], A0h, w.x, w.y);   // hi*hi
                mma_bf16(acc[0][nf], A0l, w.x, w.y);   // lo*hi
                mma_bf16(acc[0][nf], A0h, w.z, w.w);   // hi*lo
                mma_bf16(acc[1][nf], A1h, w.x, w.y);
                mma_bf16(acc[1][nf], A1l, w.x, w.y);
                mma_bf16(acc[1][nf], A1h, w.z, w.w);
            }
            if (kg < 7) { A0h = N0h; A0l = N0l; A1h = N1h; A1l = N1l; }
        }

        // write split-K partials (fp32)
        {
            float* pb = &g_part[pk][0][0];
            const int cb = nt * 128 + nh * 64 + (lane & 3) * 2;
#pragma unroll
            for (int mi = 0; mi < 2; mi++) {
                const int r = mh * 32 + mi * 16 + (lane >> 2);
#pragma unroll
                for (int nf = 0; nf < 8; nf++) {
                    const int c = cb + nf * 8;
                    *(float2*)&pb[(size_t)r * DH + c] =
                        make_float2(acc[mi][nf][0], acc[mi][nf][1]);
                    *(float2*)&pb[(size_t)(r + 8) * DH + c] =
                        make_float2(acc[mi][nf][2], acc[mi][nf][3]);
                }
            }
        }
        grid_bar();

        if (tid < 128) epilogue(s, pv00, pv01, pv10, pv11, true);
        grid_bar();
    }
}

// ---------------------------------------------------------------------------
// Kernel 3: y = g_h @ W_h2y^T + b_h2y, 8-way split-K + atomicAdd.
// ---------------------------------------------------------------------------
__global__ void k_out_init(const float* __restrict__ bias, float* __restrict__ Y) {
    int idx = blockIdx.x * 256 + threadIdx.x;
    Y[idx] = bias[idx & (DOUT - 1)];
}

__global__ __launch_bounds__(128) void k_out(const float* __restrict__ W,
                                             float* __restrict__ Y) {
    __shared__ float Hs[16][32];
    __shared__ float Ws[16][32];
    const int n0  = blockIdx.x * 32;
    const int m0  = blockIdx.y * 32;
    const int kc0 = blockIdx.z * (DH / 8);
    const int t   = threadIdx.x;
    const int nx = t & 15, my = t >> 4;
    const float* __restrict__ Hin = g_h;
    const int lrow = t >> 2;
    const int lkq  = t & 3;

    float2 acc[2][2] = { { make_float2(0.f, 0.f), make_float2(0.f, 0.f) },
                         { make_float2(0.f, 0.f), make_float2(0.f, 0.f) } };

    for (int k0 = kc0; k0 < kc0 + DH / 8; k0 += 16) {
        float4 va = *(const float4*)(Hin + (size_t)(m0 + lrow) * DH + k0 + lkq * 4);
        float4 vb = *(const float4*)(W   + (size_t)(n0 + lrow) * DH + k0 + lkq * 4);
        __syncthreads();
        Hs[lkq*4+0][lrow] = va.x; Hs[lkq*4+1][lrow] = va.y;
        Hs[lkq*4+2][lrow] = va.z; Hs[lkq*4+3][lrow] = va.w;
        Ws[lkq*4+0][lrow] = vb.x; Ws[lkq*4+1][lrow] = vb.y;
        Ws[lkq*4+2][lrow] = vb.z; Ws[lkq*4+3][lrow] = vb.w;
        __syncthreads();

#pragma unroll
        for (int kk = 0; kk < 16; kk++) {
            float4 a = *(const float4*)&Hs[kk][my*4];
            float2 bq = *(const float2*)&Ws[kk][nx*2];
            float2 ap0 = make_float2(a.x, a.y), ap1 = make_float2(a.z, a.w);
            float2 b0  = make_float2(bq.x, bq.x), b1  = make_float2(bq.y, bq.y);
            acc[0][0] = ffma2(ap0, b0, acc[0][0]);
            acc[1][0] = ffma2(ap1, b0, acc[1][0]);
            acc[0][1] = ffma2(ap0, b1, acc[0][1]);
            acc[1][1] = ffma2(ap1, b1, acc[1][1]);
        }
    }

    const int c0 = n0 + nx*2;
#pragma unroll
    for (int i = 0; i < 4; i++) {
        int m = m0 + my*4 + i;
        float v0 = (i & 1) ? acc[i>>1][0].y : acc[i>>1][0].x;
        float v1 = (i & 1) ? acc[i>>1][1].y : acc[i>>1][1].x;
        atomicAdd(&Y[(size_t)m * DOUT + c0],     v0);
        atomicAdd(&Y[(size_t)m * DOUT + c0 + 1], v1);
    }
}

// ---------------------------------------------------------------------------
extern "C" void kernel_launch(void* const* d_in, const int* in_sizes, int n_in,
                              void* d_out, int out_size) {
    (void)in_sizes; (void)n_in; (void)out_size;
    const float* x     = (const float*)d_in[0];
    const float* W_x2h = (const float*)d_in[1];
    const float* b_x2h = (const float*)d_in[2];
    const float* W_h2h = (const float*)d_in[3];
    const float* W_h2y = (const float*)d_in[4];
    const float* b_h2y = (const float*)d_in[5];
    float* y = (float*)d_out;

    cudaFuncSetAttribute(k_recur, cudaFuncAttributeMaxDynamicSharedMemorySize,
                         WTILE_U4 * sizeof(uint4));
    cudaFuncSetAttribute(k_xh_tc, cudaFuncAttributeMaxDynamicSharedMemorySize,
                         65536);

    // 1) input projection (bf16x3 tensor cores) + W bf16 hi/lo fragment pack
    k_xh_tc<<<dim3(DH / 128, M1 / 128), 256, 65536>>>(x, W_x2h, b_x2h);
    k_packw<<<(NBLK * WTILE_U4) / 256, 256>>>(W_h2h);

    // 2) all 512 recurrence steps in ONE persistent kernel (bf16x3 MMA,
    //    W-in-SMEM persistent, L2-direct A fragments, 16-way split-K)
    k_recur<<<NBLK, NTHR, WTILE_U4 * sizeof(uint4)>>>();

    // 3) output projection (split-K + atomics over bias-initialized Y)
    k_out_init<<<(B_ * DOUT) / 256, 256>>>(b_h2y, y);
    k_out<<<dim3(DOUT / 32, B_ / 32, 8), 128>>>(W_h2y, y);
}

// round 15
// speedup vs baseline: 1.0044x; 1.0044x over previous
#include <cuda_runtime.h>
#include <cuda_bf16.h>
#include <cstdint>
#include <cstddef>

#define B_   64
#define T_   512
#define DIN  1024
#define DH   2048
#define DOUT 1024
#define M1   (B_ * T_)   // 32768

// Recurrence persistent kernel: 128 blocks = 16 ntiles(128 col) x 8 kchunks(256 K)
#define NBLK    128
#define NTHR    256      // 8 warps: (kh, mh, nh)
#define KGG     128      // k16-groups over DH
#define WTILE_U4 8192    // W tile uint4s per block (128KB)

// ---------------------------------------------------------------------------
// Device globals (allocation-free scratch)
// ---------------------------------------------------------------------------
__device__ float    g_xh[(size_t)M1 * DH];        // 256 MB input projection (fp32)
__device__ float    g_h[B_ * DH];                 // final hidden state (fp32)
// W_h2h bf16 hi/lo packed in m16n8k16 B-fragment order, per block tile:
// uint4 {b0_hi, b1_hi, b0_lo, b1_lo} per (block, kg, nfl, lane)
__device__ uint4    g_Wf[(size_t)NBLK * WTILE_U4];   // 16 MB
// h bf16 hi/lo packed in A-fragment order:
// uint4 {a0,a1,a2,a3} per (kgg, mf, plane, lane)
__device__ uint4    g_hf[KGG * 4 * 2 * 32];          // 512 KB
__device__ float    g_part[16][B_][DH];              // split-K partials, 8 MB
__device__ unsigned g_bar_count;
__device__ unsigned g_bar_phase;

__device__ __forceinline__ float2 ffma2(float2 a, float2 b, float2 c) {
    float2 d;
    asm("fma.rn.f32x2 %0, %1, %2, %3;"
        : "=l"(reinterpret_cast<unsigned long long&>(d))
        : "l"(reinterpret_cast<unsigned long long&>(a)),
          "l"(reinterpret_cast<unsigned long long&>(b)),
          "l"(reinterpret_cast<unsigned long long&>(c)));
    return d;
}

// split (v0, v1) into bf16 hi plane + bf16 lo (residual) plane, packed bf16x2
__device__ __forceinline__ void split2(float v0, float v1,
                                       unsigned& hi, unsigned& lo) {
    __nv_bfloat162 h2 = __floats2bfloat162_rn(v0, v1);
    float2 hf = __bfloat1622float2(h2);
    __nv_bfloat162 l2 = __floats2bfloat162_rn(v0 - hf.x, v1 - hf.y);
    hi = *reinterpret_cast<unsigned*>(&h2);
    lo = *reinterpret_cast<unsigned*>(&l2);
}

__device__ __forceinline__ void mma_bf16(float* c, const uint4& a,
                                         unsigned b0, unsigned b1) {
    asm volatile(
        "mma.sync.aligned.m16n8k16.row.col.f32.bf16.bf16.f32 "
        "{%0,%1,%2,%3}, {%4,%5,%6,%7}, {%8,%9}, {%0,%1,%2,%3};"
        : "+f"(c[0]), "+f"(c[1]), "+f"(c[2]), "+f"(c[3])
        : "r"(a.x), "r"(a.y), "r"(a.z), "r"(a.w), "r"(b0), "r"(b1));
}

// ---------------------------------------------------------------------------
// Kernel 1 (NEW): g_xh = x @ W_x2h^T + b_x2h via bf16x3 tensor-core MMA.
// 128x128 tile, Kc=32 double-buffered fragment-order SMEM, 8 warps (4m x 2n).
// ---------------------------------------------------------------------------
__global__ __launch_bounds__(256) void k_xh_tc(const float* __restrict__ A,
                                               const float* __restrict__ W,
                                               const float* __restrict__ bias) {
    extern __shared__ uint4 smem[];
    uint4* sA = smem;          // [buf][kg][mf 0..7][plane 0..1][lane] : 2048 uint4
    uint4* sB = smem + 2048;   // [buf][kg][nfl 0..15][lane]          : 2048 uint4

    const int tid  = threadIdx.x;
    const int warp = tid >> 5;
    const int lane = tid & 31;
    const int wm = warp >> 1;      // 0..3 : rows wm*32..+31
    const int wn = warp & 1;       // 0..1 : cols wn*64..+63
    const int m0 = blockIdx.y * 128;
    const int n0 = blockIdx.x * 128;
    const int lr = lane >> 2;      // 0..7
    const int lk = (lane & 3) * 2;

    // loader base pointers (thread owns: A item (mf=warp, lane), kg 0/1;
    //                                  W items (nfl=warp, warp+8, lane), kg 0/1)
    const float* Ab = A + (size_t)(m0 + warp * 16 + lr) * DIN + lk;
    const float* Wb0 = W + (size_t)(n0 + warp * 8 + lr) * DIN + lk;
    const float* Wb1 = W + (size_t)(n0 + (warp + 8) * 8 + lr) * DIN + lk;

    float acc[2][8][4];
#pragma unroll
    for (int mi = 0; mi < 2; mi++)
#pragma unroll
        for (int nf = 0; nf < 8; nf++)
#pragma unroll
            for (int i = 0; i < 4; i++) acc[mi][nf][i] = 0.f;

    float2 ax[2][4];        // [kg][{(r,k),(r+8,k),(r,k+8),(r+8,k+8)}]
    float2 wx[2][2][2];     // [kg][nfl half][k01 / k89]

    auto gload = [&](int kc) {
#pragma unroll
        for (int kg = 0; kg < 2; kg++) {
            const float* ap = Ab + kc + kg * 16;
            ax[kg][0] = __ldg((const float2*)ap);
            ax[kg][1] = __ldg((const float2*)(ap + 8 * DIN));
            ax[kg][2] = __ldg((const float2*)(ap + 8));
            ax[kg][3] = __ldg((const float2*)(ap + 8 * DIN + 8));
            const float* wp0 = Wb0 + kc + kg * 16;
            const float* wp1 = Wb1 + kc + kg * 16;
            wx[kg][0][0] = __ldg((const float2*)wp0);
            wx[kg][0][1] = __ldg((const float2*)(wp0 + 8));
            wx[kg][1][0] = __ldg((const float2*)wp1);
            wx[kg][1][1] = __ldg((const float2*)(wp1 + 8));
        }
    };

    auto sstore = [&](int buf) {
#pragma unroll
        for (int kg = 0; kg < 2; kg++) {
            uint4 hi, lo;
            split2(ax[kg][0].x, ax[kg][0].y, hi.x, lo.x);
            split2(ax[kg][1].x, ax[kg][1].y, hi.y, lo.y);
            split2(ax[kg][2].x, ax[kg][2].y, hi.z, lo.z);
            split2(ax[kg][3].x, ax[kg][3].y, hi.w, lo.w);
            sA[buf * 1024 + kg * 512 + warp * 64 + lane]      = hi;
            sA[buf * 1024 + kg * 512 + warp * 64 + 32 + lane] = lo;
            uint4 v0, v1;
            split2(wx[kg][0][0].x, wx[kg][0][0].y, v0.x, v0.z);
            split2(wx[kg][0][1].x, wx[kg][0][1].y, v0.y, v0.w);
            split2(wx[kg][1][0].x, wx[kg][1][0].y, v1.x, v1.z);
            split2(wx[kg][1][1].x, wx[kg][1][1].y, v1.y, v1.w);
            sB[buf * 1024 + kg * 512 + warp * 32 + lane]       = v0;
            sB[buf * 1024 + kg * 512 + (warp + 8) * 32 + lane] = v1;
        }
    };

    auto compute = [&](int buf) {
#pragma unroll
        for (int kg = 0; kg < 2; kg++) {
            const int ab = buf * 1024 + kg * 512;
            uint4 Ah0 = sA[ab + (wm * 2) * 64 + lane];
            uint4 Al0 = sA[ab + (wm * 2) * 64 + 32 + lane];
            uint4 Ah1 = sA[ab + (wm * 2 + 1) * 64 + lane];
            uint4 Al1 = sA[ab + (wm * 2 + 1) * 64 + 32 + lane];
#pragma unroll
            for (int nf = 0; nf < 8; nf++) {
                uint4 w = sB[ab + (wn * 8 + nf) * 32 + lane];
                mma_bf16(acc[0][nf], Ah0, w.x, w.y);   // hi*hi
                mma_bf16(acc[0][nf], Al0, w.x, w.y);   // lo*hi
                mma_bf16(acc[0][nf], Ah0, w.z, w.w);   // hi*lo
                mma_bf16(acc[1][nf], Ah1, w.x, w.y);
                mma_bf16(acc[1][nf], Al1, w.x, w.y);
                mma_bf16(acc[1][nf], Ah1, w.z, w.w);
            }
        }
    };

    gload(0);
    sstore(0);
    __syncthreads();

    for (int kc = 0; kc < DIN; kc += 32) {
        const int buf = (kc >> 5) & 1;
        const bool more = (kc + 32) < DIN;
        if (more) gload(kc + 32);
        compute(buf);
        if (more) sstore(buf ^ 1);
        __syncthreads();
    }

    // epilogue: add bias, store fp32
#pragma unroll
    for (int nf = 0; nf < 8; nf++) {
        const int c = n0 + wn * 64 + nf * 8 + lk;
        float2 bb = __ldg((const float2*)(bias + c));
#pragma unroll
        for (int mi = 0; mi < 2; mi++) {
            const int r = m0 + wm * 32 + mi * 16 + lr;
            *(float2*)(g_xh + (size_t)r * DH + c) =
                make_float2(acc[mi][nf][0] + bb.x, acc[mi][nf][1] + bb.y);
            *(float2*)(g_xh + (size_t)(r + 8) * DH + c) =
                make_float2(acc[mi][nf][2] + bb.x, acc[mi][nf][3] + bb.y);
        }
    }
}

// ---------------------------------------------------------------------------
// Pack W_h2h into bf16 hi/lo B-fragment order (per-block 128KB tiles).
// ---------------------------------------------------------------------------
__global__ void k_packw(const float* __restrict__ W) {
    size_t u = (size_t)blockIdx.x * 256 + threadIdx.x;   // 0 .. 1M-1
    int b    = (int)(u >> 13);
    int r    = (int)(u & 8191);
    int kg   = r >> 9;          // 0..15
    int nfl  = (r >> 5) & 15;   // 0..15
    int lane = r & 31;
    int nt = b >> 3, kch = b & 7;
    int n = nt * 128 + nfl * 8 + (lane >> 2);
    int k = kch * 256 + kg * 16 + (lane & 3) * 2;
    const float* row = W + (size_t)n * DH;
    float w0 = row[k],     w1 = row[k + 1];
    float w2 = row[k + 8], w3 = row[k + 9];
    uint4 v;
    unsigned lo01, lo89;
    split2(w0, w1, v.x, lo01);
    split2(w2, w3, v.y, lo89);
    v.z = lo01;
    v.w = lo89;
    g_Wf[u] = v;
}

// ---------------------------------------------------------------------------
// Persistent recurrence kernel: bf16x3 mma.m16n8k16, W tile persistent in SMEM,
// 8 warps (2/SMSP), A fragments L2-direct, 16-way split-K partials.
// xh loads for the epilogue are hoisted above the MMA phase (DRAM latency hide).
// ---------------------------------------------------------------------------
__global__ __launch_bounds__(NTHR, 1) void k_recur() {
    extern __shared__ uint4 sW[];   // 8192 uint4 = 128 KB

    const int tid  = threadIdx.x;
    const int b    = blockIdx.x;
    const int warp = tid >> 5;
    const int lane = tid & 31;
    const int kh = warp >> 2;          // k-half (0/1): 128 K each
    const int mh = (warp >> 1) & 1;    // m-half: rows mh*32..+31
    const int nh = warp & 1;           // n-half: cols nh*64..+63
    const int nt  = b >> 3;            // ntile 0..15
    const int kch = b & 7;             // kchunk 0..7
    const int pk  = kch * 2 + kh;      // partial buffer index

    // Load persistent W tile into SMEM (once)
    {
        const uint4* wsrc = g_Wf + (size_t)b * WTILE_U4;
        for (int i = tid; i < WTILE_U4; i += NTHR) sW[i] = __ldg(wsrc + i);
    }

    // replay-safe grid barrier
    unsigned bar_base;
    asm volatile("ld.acquire.gpu.global.u32 %0, [%1];"
                 : "=r"(bar_base) : "l"(&g_bar_phase));
    unsigned bar_t = 0;

    auto grid_bar = [&]() {
        bar_t++;
        __syncthreads();
        __threadfence();
        if (tid == 0) {
            unsigned arr = atomicAdd(&g_bar_count, 1);
            if (arr == NBLK - 1) {
                atomicExch(&g_bar_count, 0);
                __threadfence();
                atomicAdd(&g_bar_phase, 1);
            } else {
                unsigned p;
                do {
                    __nanosleep(32);
                    asm volatile("ld.acquire.gpu.global.u32 %0, [%1];"
                                 : "=r"(p) : "l"(&g_bar_phase));
                } while (p - bar_base < bar_t);
            }
        }
        __syncthreads();
    };

    // Epilogue mapping: block b owns kgg = b (16 h-columns), threads 0..127
    const int elane = tid & 31;
    const int emf   = (tid >> 5) & 3;
    const int er    = emf * 16 + (elane >> 2);       // row (and +8)
    const int ek0   = b * 16 + (elane & 3) * 2;      // col (and +1, +8, +9)
    uint4* hf_hi = g_hf + ((b * 4 + emf) * 2 + 0) * 32 + elane;
    uint4* hf_lo = g_hf + ((b * 4 + emf) * 2 + 1) * 32 + elane;

    // preloaded xh values for epilogue of step s (loads xh_{s-1})
    auto xh_load = [&](int s, float2& v00, float2& v01, float2& v10, float2& v11) {
        const float* x0 = &g_xh[((size_t)er * T_ + (s - 1)) * DH + ek0];
        const float* x1 = &g_xh[((size_t)(er + 8) * T_ + (s - 1)) * DH + ek0];
        v00 = __ldg((const float2*)x0);
        v01 = __ldg((const float2*)(x0 + 8));
        v10 = __ldg((const float2*)x1);
        v11 = __ldg((const float2*)(x1 + 8));
    };

    auto epilogue = [&](int s, float2 v00, float2 v01, float2 v10, float2 v11,
                        bool addp) {
        if (addp) {
#pragma unroll
            for (int p = 0; p < 16; p++) {
                const float* pb = &g_part[p][0][0];
                const float* p0 = pb + (size_t)er * DH + ek0;
                const float* p1 = pb + (size_t)(er + 8) * DH + ek0;
                float2 q;
                q = __ldcg((const float2*)p0);       v00.x += q.x; v00.y += q.y;
                q = __ldcg((const float2*)(p0 + 8)); v01.x += q.x; v01.y += q.y;
                q = __ldcg((const float2*)p1);       v10.x += q.x; v10.y += q.y;
                q = __ldcg((const float2*)(p1 + 8)); v11.x += q.x; v11.y += q.y;
            }
        }
        v00.x = fmaxf(v00.x, 0.f); v00.y = fmaxf(v00.y, 0.f);
        v01.x = fmaxf(v01.x, 0.f); v01.y = fmaxf(v01.y, 0.f);
        v10.x = fmaxf(v10.x, 0.f); v10.y = fmaxf(v10.y, 0.f);
        v11.x = fmaxf(v11.x, 0.f); v11.y = fmaxf(v11.y, 0.f);
        uint4 hi, lo;
        split2(v00.x, v00.y, hi.x, lo.x);   // a0: (r,   k0,k0+1)
        split2(v10.x, v10.y, hi.y, lo.y);   // a1: (r+8, k0,k0+1)
        split2(v01.x, v01.y, hi.z, lo.z);   // a2: (r,   k0+8,k0+9)
        split2(v11.x, v11.y, hi.w, lo.w);   // a3: (r+8, k0+8,k0+9)
        *hf_hi = hi;
        *hf_lo = lo;
        if (s == T_) {
            *(float2*)&g_h[(size_t)er * DH + ek0]           = v00;
            *(float2*)&g_h[(size_t)er * DH + ek0 + 8]       = v01;
            *(float2*)&g_h[(size_t)(er + 8) * DH + ek0]     = v10;
            *(float2*)&g_h[(size_t)(er + 8) * DH + ek0 + 8] = v11;
        }
    };

    if (tid < 128) {   // h_1 = relu(xh_0)
        float2 v00, v01, v10, v11;
        xh_load(1, v00, v01, v10, v11);
        epilogue(1, v00, v01, v10, v11, false);
    }
    grid_bar();

    const int kggbase = kch * 16 + kh * 8;

    for (int s = 2; s <= T_; s++) {
        // hoisted epilogue xh loads for this step (hide DRAM latency under MMA)
        float2 pv00, pv01, pv10, pv11;
        if (tid < 128) xh_load(s, pv00, pv01, pv10, pv11);

        // ---- MMA phase: partial[pk] = h_{s-1}[:, kslice] @ W[ntile, kslice]^T
        float acc[2][8][4];
#pragma unroll
        for (int mi = 0; mi < 2; mi++)
#pragma unroll
            for (int nf = 0; nf < 8; nf++)
#pragma unroll
                for (int i = 0; i < 4; i++) acc[mi][nf][i] = 0.f;

        // prefetch kg=0 A fragments
        const uint4* ab0 = g_hf + ((kggbase * 4 + mh * 2) * 2) * 32 + lane;
        uint4 A0h = __ldcg(ab0);
        uint4 A0l = __ldcg(ab0 + 32);
        uint4 A1h = __ldcg(ab0 + 64);
        uint4 A1l = __ldcg(ab0 + 96);

#pragma unroll
        for (int kg = 0; kg < 8; kg++) {
            uint4 N0h, N0l, N1h, N1l;
            if (kg < 7) {
                const uint4* ab =
                    g_hf + (((kggbase + kg + 1) * 4 + mh * 2) * 2) * 32 + lane;
                N0h = __ldcg(ab);
                N0l = __ldcg(ab + 32);
                N1h = __ldcg(ab + 64);
                N1l = __ldcg(ab + 96);
            }
            const int wb = ((kh * 8 + kg) * 16 + nh * 8) * 32 + lane;
#pragma unroll
            for (int nf = 0; nf < 8; nf++) {
                uint4 w = sW[wb + nf * 32];
                mma_bf16(acc[0][nf], A0h, w.x, w.y);   // hi*hi
                mma_bf16(acc[0][nf], A0l, w.x, w.y);   // lo*hi
                mma_bf16(acc[0][nf], A0h, w.z, w.w);   // hi*lo
                mma_bf16(acc[1][nf], A1h, w.x, w.y);
                mma_bf16(acc[1][nf], A1l, w.x, w.y);
                mma_bf16(acc[1][nf], A1h, w.z, w.w);
            }
            if (kg < 7) { A0h = N0h; A0l = N0l; A1h = N1h; A1l = N1l; }
        }

        // write split-K partials (fp32)
        {
            float* pb = &g_part[pk][0][0];
            const int cb = nt * 128 + nh * 64 + (lane & 3) * 2;
#pragma unroll
            for (int mi = 0; mi < 2; mi++) {
                const int r = mh * 32 + mi * 16 + (lane >> 2);
#pragma unroll
                for (int nf = 0; nf < 8; nf++) {
                    const int c = cb + nf * 8;
                    *(float2*)&pb[(size_t)r * DH + c] =
                        make_float2(acc[mi][nf][0], acc[mi][nf][1]);
                    *(float2*)&pb[(size_t)(r + 8) * DH + c] =
                        make_float2(acc[mi][nf][2], acc[mi][nf][3]);
                }
            }
        }
        grid_bar();

        if (tid < 128) epilogue(s, pv00, pv01, pv10, pv11, true);
        grid_bar();
    }
}

// ---------------------------------------------------------------------------
// Kernel 3: y = g_h @ W_h2y^T + b_h2y, 8-way split-K + atomicAdd.
// ---------------------------------------------------------------------------
__global__ void k_out_init(const float* __restrict__ bias, float* __restrict__ Y) {
    int idx = blockIdx.x * 256 + threadIdx.x;
    Y[idx] = bias[idx & (DOUT - 1)];
}

__global__ __launch_bounds__(128) void k_out(const float* __restrict__ W,
                                             float* __restrict__ Y) {
    __shared__ float Hs[16][32];
    __shared__ float Ws[16][32];
    const int n0  = blockIdx.x * 32;
    const int m0  = blockIdx.y * 32;
    const int kc0 = blockIdx.z * (DH / 8);
    const int t   = threadIdx.x;
    const int nx = t & 15, my = t >> 4;
    const float* __restrict__ Hin = g_h;
    const int lrow = t >> 2;
    const int lkq  = t & 3;

    float2 acc[2][2] = { { make_float2(0.f, 0.f), make_float2(0.f, 0.f) },
                         { make_float2(0.f, 0.f), make_float2(0.f, 0.f) } };

    for (int k0 = kc0; k0 < kc0 + DH / 8; k0 += 16) {
        float4 va = *(const float4*)(Hin + (size_t)(m0 + lrow) * DH + k0 + lkq * 4);
        float4 vb = *(const float4*)(W   + (size_t)(n0 + lrow) * DH + k0 + lkq * 4);
        __syncthreads();
        Hs[lkq*4+0][lrow] = va.x; Hs[lkq*4+1][lrow] = va.y;
        Hs[lkq*4+2][lrow] = va.z; Hs[lkq*4+3][lrow] = va.w;
        Ws[lkq*4+0][lrow] = vb.x; Ws[lkq*4+1][lrow] = vb.y;
        Ws[lkq*4+2][lrow] = vb.z; Ws[lkq*4+3][lrow] = vb.w;
        __syncthreads();

#pragma unroll
        for (int kk = 0; kk < 16; kk++) {
            float4 a = *(const float4*)&Hs[kk][my*4];
            float2 bq = *(const float2*)&Ws[kk][nx*2];
            float2 ap0 = make_float2(a.x, a.y), ap1 = make_float2(a.z, a.w);
            float2 b0  = make_float2(bq.x, bq.x), b1  = make_float2(bq.y, bq.y);
            acc[0][0] = ffma2(ap0, b0, acc[0][0]);
            acc[1][0] = ffma2(ap1, b0, acc[1][0]);
            acc[0][1] = ffma2(ap0, b1, acc[0][1]);
            acc[1][1] = ffma2(ap1, b1, acc[1][1]);
        }
    }

    const int c0 = n0 + nx*2;
#pragma unroll
    for (int i = 0; i < 4; i++) {
        int m = m0 + my*4 + i;
        float v0 = (i & 1) ? acc[i>>1][0].y : acc[i>>1][0].x;
        float v1 = (i & 1) ? acc[i>>1][1].y : acc[i>>1][1].x;
        atomicAdd(&Y[(size_t)m * DOUT + c0],     v0);
        atomicAdd(&Y[(size_t)m * DOUT + c0 + 1], v1);
    }
}

// ---------------------------------------------------------------------------
extern "C" void kernel_launch(void* const* d_in, const int* in_sizes, int n_in,
                              void* d_out, int out_size) {
    (void)in_sizes; (void)n_in; (void)out_size;
    const float* x     = (const float*)d_in[0];
    const float* W_x2h = (const float*)d_in[1];
    const float* b_x2h = (const float*)d_in[2];
    const float* W_h2h = (const float*)d_in[3];
    const float* W_h2y = (const float*)d_in[4];
    const float* b_h2y = (const float*)d_in[5];
    float* y = (float*)d_out;

    cudaFuncSetAttribute(k_recur, cudaFuncAttributeMaxDynamicSharedMemorySize,
                         WTILE_U4 * sizeof(uint4));
    cudaFuncSetAttribute(k_xh_tc, cudaFuncAttributeMaxDynamicSharedMemorySize,
                         65536);

    // 1) input projection (bf16x3 tensor cores) + W bf16 hi/lo fragment pack
    k_xh_tc<<<dim3(DH / 128, M1 / 128), 256, 65536>>>(x, W_x2h, b_x2h);
    k_packw<<<(NBLK * WTILE_U4) / 256, 256>>>(W_h2h);

    // 2) all 512 recurrence steps in ONE persistent kernel (bf16x3 MMA,
    //    W-in-SMEM persistent, L2-direct A fragments, 16-way split-K)
    k_recur<<<NBLK, NTHR, WTILE_U4 * sizeof(uint4)>>>();

    // 3) output projection (split-K + atomics over bias-initialized Y)
    k_out_init<<<(B_ * DOUT) / 256, 256>>>(b_h2y, y);
    k_out<<<dim3(DOUT / 32, B_ / 32, 8), 128>>>(W_h2y, y);
}